// round 5
// baseline (speedup 1.0000x reference)
#include <cuda_runtime.h>
#include <math.h>

#define TOPK 13
#define EPSF 1e-7f
#define MAX_BN (1 << 20)
#define MAX_B 64
#define MAX_LIST 16384
#define NBLK 148

typedef unsigned long long u64;

__device__ u64 g_key[MAX_BN];
__device__ double g_acc[MAX_B * 8];
__device__ int g_cnt;
__device__ int g_bar1;
__device__ int g_bar2;
__device__ int2 g_list[MAX_LIST];

__device__ __forceinline__ float iou_fn(float4 a, float4 b) {
    float x1 = fmaxf(a.x, b.x), y1 = fmaxf(a.y, b.y);
    float x2 = fminf(a.z, b.z), y2 = fminf(a.w, b.w);
    float inter = fmaxf(x2 - x1, 0.0f) * fmaxf(y2 - y1, 0.0f);
    float aa = (a.z - a.x) * (a.w - a.y);
    float ab = (b.z - b.x) * (b.w - b.y);
    return inter / (aa + ab - inter + EPSF);
}

// bce += max(s,0)+log1p(exp(-|s|)); ps += sigmoid(s). 1 MUFU + FMA polys.
__device__ __forceinline__ void score_terms(float s, float& bce, float& ps) {
    float as = fabsf(s);
    float e = __expf(-as);                       // (0,1]
    float de = 2.0f + e;
    float r = __fmaf_rn(e, -0.16666667f, 0.5f);  // seed 1/(2+e)
    r = r * (2.0f - de * r);
    r = r * (2.0f - de * r);
    float w = e * r;                             // w = e/(2+e) in (0, 1/3]
    float w2 = w * w;
    float p = 0.22222222f;
    p = __fmaf_rn(p, w2, 0.28571430f);
    p = __fmaf_rn(p, w2, 0.40000000f);
    p = __fmaf_rn(p, w2, 0.66666667f);
    p = __fmaf_rn(p, w2, 2.0f);
    bce += fmaxf(s, 0.0f) + w * p;               // ln(1+e) = 2 atanh(w)
    float y = 1.0f + w;
    float q = 2.0f - y;
    q = q * (2.0f - y * q);
    q = q * (2.0f - y * q);
    q = q * (2.0f - y * q);
    float pa = (1.0f - w) * q;                   // sigmoid(|s|)
    ps += (s >= 0.0f) ? pa : (1.0f - pa);
}

__global__ __launch_bounds__(256) void k_all(
    const float4* __restrict__ pred_boxes, const float* __restrict__ scores,
    const float2* __restrict__ anchors, const float* __restrict__ strides,
    const float* __restrict__ logits, const float* __restrict__ prompt,
    const float4* __restrict__ gts, const int* __restrict__ img_p,
    float* __restrict__ out, int B, int N, int G, int P)
{
    int t = threadIdx.x;
    int lane = t & 31, wid = t >> 5;
    int nb = gridDim.x;
    int BG = B * G;
    int total = B * N;

    // ================= phase 1: dense score sums (all blocks) =================
    {
        int nv4 = total >> 2;
        float bce = 0.0f, ps = 0.0f;
        for (int i = blockIdx.x * 256 + t; i < nv4; i += nb * 256) {
            float4 s4 = ((const float4*)scores)[i];
            score_terms(s4.x, bce, ps);
            score_terms(s4.y, bce, ps);
            score_terms(s4.z, bce, ps);
            score_terms(s4.w, bce, ps);
        }
        int tail = total & 3;
        if (blockIdx.x == 0 && t < tail) score_terms(scores[total - tail + t], bce, ps);

        __shared__ float r0[8], r1[8];
#pragma unroll
        for (int off = 16; off > 0; off >>= 1) {
            bce += __shfl_down_sync(0xFFFFFFFFu, bce, off);
            ps  += __shfl_down_sync(0xFFFFFFFFu, ps, off);
        }
        if (lane == 0) { r0[wid] = bce; r1[wid] = ps; }
        __syncthreads();
        if (t == 0) {
            float a = 0.0f, p = 0.0f;
            for (int w = 0; w < 8; w++) { a += r0[w]; p += r1[w]; }
            atomicAdd(&g_acc[0], (double)a);
            atomicAdd(&g_acc[3], (double)p);
        }
    }

    // ================= phase 2: assignment (warp per (b,g)) =================
    {
        int img = img_p[0];
        int n0 = img / 8, n1 = img / 16, n2 = img / 32;
        bool structured = (n0 * n0 + n1 * n1 + n2 * n2 == N) && img > 0;

        for (int bg = blockIdx.x * 8 + wid; bg < BG; bg += nb * 8) {
            int b = bg / G, g = bg % G;
            float4 gt = gts[bg];

            u64 v[TOPK];
#pragma unroll
            for (int j = 0; j < TOPK; j++) v[j] = 0ULL;

            const float4* pb_b = pred_boxes + (size_t)b * N;
            const float*  sc_b = scores + (size_t)b * N;

            if (structured) {
                int nn0[3] = {n0, n1, n2};
                int bb0[3] = {0, n0 * n0, n0 * n0 + n1 * n1};
#pragma unroll
                for (int sc = 0; sc < 3; sc++) {
                    float s = (float)(8 << sc);
                    int n = nn0[sc];
                    int cl = max((int)floorf(gt.x / s - 0.5f) - 1, 0);
                    int ch = min((int)ceilf(gt.z / s - 0.5f) + 1, n - 1);
                    int rl = max((int)floorf(gt.y / s - 0.5f) - 1, 0);
                    int rh = min((int)ceilf(gt.w / s - 0.5f) + 1, n - 1);
                    int cw = ch - cl + 1, rw = rh - rl + 1;
                    if (cw <= 0 || rw <= 0) continue;
                    int m = cw * rw;
                    for (int k = lane; k < m; k += 32) {
                        int row = k / cw + rl;
                        int col = k - (k / cw) * cw + cl;
                        int a = bb0[sc] + row * n + col;
                        float2 an = anchors[a];
                        if (an.x >= gt.x && an.x <= gt.z && an.y >= gt.y && an.y <= gt.w) {
                            float4 pb = pb_b[a];
                            float iou = iou_fn(pb, gt);
                            float sv = sc_b[a];
                            float prob = 1.0f / (1.0f + __expf(-sv));
                            float i2 = iou * iou;
                            float align = prob * (i2 * i2 * i2);
                            u64 key = ((u64)__float_as_uint(align) << 32)
                                    | (u64)(0xFFFFFFFFu - (unsigned)a);
                            if (key > v[TOPK - 1]) {
#pragma unroll
                                for (int j = 0; j < TOPK; j++)
                                    if (key > v[j]) { u64 tv = v[j]; v[j] = key; key = tv; }
                            }
                        }
                    }
                }
            } else {
                for (int a = lane; a < N; a += 32) {
                    float2 an = anchors[a];
                    if (an.x >= gt.x && an.x <= gt.z && an.y >= gt.y && an.y <= gt.w) {
                        float4 pb = pb_b[a];
                        float iou = iou_fn(pb, gt);
                        float sv = sc_b[a];
                        float prob = 1.0f / (1.0f + __expf(-sv));
                        float i2 = iou * iou;
                        float align = prob * (i2 * i2 * i2);
                        u64 key = ((u64)__float_as_uint(align) << 32)
                                | (u64)(0xFFFFFFFFu - (unsigned)a);
                        if (key > v[TOPK - 1]) {
#pragma unroll
                            for (int j = 0; j < TOPK; j++)
                                if (key > v[j]) { u64 tv = v[j]; v[j] = key; key = tv; }
                        }
                    }
                }
            }

            // warp top-13 merge (keys unique)
            u64 myw = 0ULL;
            int ptr = 0;
            for (int r = 0; r < TOPK; r++) {
                u64 h = (ptr < TOPK) ? v[ptr] : 0ULL;
                int src = lane;
#pragma unroll
                for (int off = 16; off > 0; off >>= 1) {
                    u64 o = __shfl_down_sync(0xFFFFFFFFu, h, off);
                    int os = __shfl_down_sync(0xFFFFFFFFu, src, off);
                    if (o > h) { h = o; src = os; }
                }
                u64 hb = __shfl_sync(0xFFFFFFFFu, h, 0);
                int sb_ = __shfl_sync(0xFFFFFFFFu, src, 0);
                if (hb == 0ULL) break;
                if (lane == sb_) ptr++;
                if (lane == r) myw = hb;
            }

            if (lane < TOPK && myw != 0ULL) {
                unsigned bits = (unsigned)(myw >> 32);
                int a = (int)(0xFFFFFFFFu - (unsigned)(myw & 0xFFFFFFFFull));
                u64 key = ((u64)(bits + 1u) << 32) | (u64)(0xFFFFFFFFu - (unsigned)g);
                atomicMax(&g_key[(size_t)b * N + a], key);
                int pos = atomicAdd(&g_cnt, 1);
                if (pos < MAX_LIST) g_list[pos] = make_int2(b * N + a, g);
            }
        }
    }

    // ================= grid barrier =================
    __syncthreads();
    if (t == 0) {
        __threadfence();
        atomicAdd(&g_bar1, 1);
        while (*(volatile int*)&g_bar1 < nb) __nanosleep(64);
        __threadfence();
    }
    __syncthreads();

    // ================= phase 3: foreground terms =================
    __shared__ double acc_s[MAX_B * 8];
    for (int i = t; i < B * 8; i += 256) acc_s[i] = 0.0;
    __syncthreads();

    int cnt = g_cnt;
    if (cnt > MAX_LIST) cnt = MAX_LIST;
    for (int i = blockIdx.x * 256 + t; i < cnt; i += nb * 256) {
        int2 e = g_list[i];
        int idx = e.x, g = e.y;
        int b = idx / N, a = idx - b * N;
        u64 key = g_key[idx];
        int gw = (int)(0xFFFFFFFFu - (unsigned)(key & 0xFFFFFFFFull));
        if (key != 0ULL && gw == g) {
            g_key[idx] = 0ULL;   // winner cleans up
            float4 gt = gts[b * G + g];
            float4 pb = pred_boxes[idx];
            float s = scores[idx];
            float prob = 1.0f / (1.0f + expf(-s));
            float iou = iou_fn(pb, gt);
            float ts = fmaxf(iou, 0.1f);
            float cw = fmaxf(pb.z, gt.z) - fminf(pb.x, gt.x);
            float ch = fmaxf(pb.w, gt.w) - fminf(pb.y, gt.y);
            float c2 = cw * cw + ch * ch + EPSF;
            float dx = gt.x + gt.z - pb.x - pb.z;
            float dy = gt.y + gt.w - pb.y - pb.w;
            float rho2 = (dx * dx + dy * dy) * 0.25f;
            float w1 = pb.z - pb.x, h1 = pb.w - pb.y + EPSF;
            float w2 = gt.z - gt.x, h2 = gt.w - gt.y + EPSF;
            float dat = atanf(w2 / h2) - atanf(w1 / h1);
            float vv = 0.40528473456935109f * dat * dat;
            float alpha = vv / (vv - iou + 1.0f + EPSF);
            float ciou = iou - rho2 / c2 - vv * alpha;
            float2 an = anchors[a];
            float st = strides[a];
            float dist[4];
            dist[0] = (an.x - gt.x) / st;
            dist[1] = (an.y - gt.y) / st;
            dist[2] = (gt.z - an.x) / st;
            dist[3] = (gt.w - an.y) / st;
            const float* lg = logits + (size_t)idx * 64;
            float dflv = 0.0f;
#pragma unroll
            for (int ch_i = 0; ch_i < 4; ch_i++) {
                float x[16];
                const float4* l4 = (const float4*)(lg + ch_i * 16);
#pragma unroll
                for (int q = 0; q < 4; q++) {
                    float4 f = l4[q];
                    x[q * 4 + 0] = f.x; x[q * 4 + 1] = f.y;
                    x[q * 4 + 2] = f.z; x[q * 4 + 3] = f.w;
                }
                float m = x[0];
#pragma unroll
                for (int q = 1; q < 16; q++) m = fmaxf(m, x[q]);
                float se = 0.0f;
#pragma unroll
                for (int q = 0; q < 16; q++) se += __expf(x[q] - m);
                float logZ = m + __logf(se);
                float d = fminf(fmaxf(dist[ch_i], 0.0f), 16.0f - 1.0f - 0.01f);
                int tl = (int)d;
                int tr = min(tl + 1, 15);
                float wl = (float)tr - d;
                float wr = 1.0f - wl;
                dflv += (logZ - x[tl]) * wl + (logZ - x[tr]) * wr;
            }
            float img = fmaxf((float)img_p[0], 1.0f);
            float cx = (gt.x + gt.z) * 0.5f / img;
            float cy = (gt.y + gt.w) * 0.5f / img;
            float cn = fmaxf(sqrtf(cx * cx + cy * cy), 1e-12f);
            cx /= cn; cy /= cn;
            float p0 = prompt[(size_t)b * P + 0], p1 = prompt[(size_t)b * P + 1];
            float pn = fmaxf(sqrtf(p0 * p0 + p1 * p1), 1e-12f);
            float ctr = 1.0f - (cx * p0 + cy * p1) / pn;

            double* A = acc_s + b * 8;
            atomicAdd(&A[0], (double)(-s * ts));
            atomicAdd(&A[1], 1.0);
            atomicAdd(&A[2], (double)prob);
            atomicAdd(&A[4], (double)iou);
            atomicAdd(&A[5], (double)(1.0f - ciou));
            atomicAdd(&A[6], (double)dflv);
            atomicAdd(&A[7], (double)ctr);
        }
    }
    __syncthreads();
    for (int j = t; j < B * 8; j += 256) {
        double val = acc_s[j];
        if (val != 0.0) atomicAdd(&g_acc[j], val);
    }

    // ================= phase 4: last block finalizes =================
    __syncthreads();
    __shared__ int s_last;
    if (t == 0) {
        __threadfence();
        s_last = (atomicAdd(&g_bar2, 1) == nb - 1);
    }
    __syncthreads();
    if (!s_last) return;
    __threadfence();

    __shared__ double pm[MAX_B], pi[MAX_B], pdf[MAX_B], pc[MAX_B];
    __shared__ double pt[MAX_B], pp[MAX_B], ptot[MAX_B], pmi[MAX_B];
    if (t < B) {
        const double* A = &g_acc[t * 8];
        double np = A[1];
        double den = fmax(np, 1.0);
        pm[t] = A[0] / (double)N;
        pt[t] = np;
        pp[t] = A[2];
        ptot[t] = A[3];
        pmi[t] = A[4];
        pi[t] = A[5] / den;
        pdf[t] = A[6] / (4.0 * den);
        pc[t] = A[7] / den;
    }
    __syncthreads();
    if (t == 0) {
        double match = 0, iou = 0, dfl = 0, ctr = 0, tp = 0, pos = 0, tot = 0, mi = 0;
        for (int b = 0; b < B; b++) {
            match += pm[b]; iou += pi[b]; dfl += pdf[b]; ctr += pc[b];
            tp += pt[b]; pos += pp[b]; tot += ptot[b]; mi += pmi[b];
        }
        double nb_ = (double)B;
        double tneg = (double)B * (double)N - tp;
        out[0] = (float)((1.0 * match + 7.5 * iou + 1.5 * dfl + 1.0 * ctr) / nb_);
        out[1] = (float)(match / nb_);
        out[2] = (float)(iou / nb_);
        out[3] = (float)(dfl / nb_);
        out[4] = (float)(ctr / nb_);
        out[5] = (float)tp;
        out[6] = (float)tneg;
        out[7] = (float)(pos / fmax(tp, 1.0));
        out[8] = (float)((tot - pos) / fmax(tneg, 1.0));
        out[9] = (float)(mi / fmax(tp, 1.0));
        g_cnt = 0;
        g_bar1 = 0;
        g_bar2 = 0;
    }
    __syncthreads();
    for (int j = t; j < B * 8; j += 256) g_acc[j] = 0.0;
}

extern "C" void kernel_launch(void* const* d_in, const int* in_sizes, int n_in,
                              void* d_out, int out_size) {
    const float* pred_boxes = (const float*)d_in[0];
    const float* pred_scores = (const float*)d_in[1];
    const float* anchors = (const float*)d_in[2];
    const float* strides = (const float*)d_in[3];
    const float* logits = (const float*)d_in[4];
    const float* prompt = (const float*)d_in[5];
    const float* gts = (const float*)d_in[6];
    const int* imgp = (const int*)d_in[7];

    int N = in_sizes[2] / 2;
    int B = in_sizes[1] / N;
    int G = in_sizes[6] / (4 * B);
    int P = in_sizes[5] / B;

    k_all<<<NBLK, 256>>>((const float4*)pred_boxes, pred_scores,
                         (const float2*)anchors, strides, logits, prompt,
                         (const float4*)gts, imgp, (float*)d_out, B, N, G, P);
}

// round 6
// speedup vs baseline: 1.0450x; 1.0450x over previous
#include <cuda_runtime.h>
#include <math.h>

#define TOPK 13
#define EPSF 1e-7f
#define MAX_BN (1 << 20)
#define MAX_B 64
#define MAX_LIST 16384

typedef unsigned long long u64;

__device__ u64 g_key[MAX_BN];
__device__ double g_acc[MAX_B * 8];
__device__ int g_cnt;
__device__ int g_done;
__device__ int2 g_list[MAX_LIST];

__device__ __forceinline__ float iou_fn(float4 a, float4 b) {
    float x1 = fmaxf(a.x, b.x), y1 = fmaxf(a.y, b.y);
    float x2 = fminf(a.z, b.z), y2 = fminf(a.w, b.w);
    float inter = fmaxf(x2 - x1, 0.0f) * fmaxf(y2 - y1, 0.0f);
    float aa = (a.z - a.x) * (a.w - a.y);
    float ab = (b.z - b.x) * (b.w - b.y);
    return inter / (aa + ab - inter + EPSF);
}

// 3-MUFU fast path: exp, rcp, log.
__device__ __forceinline__ void score_terms(float s, float& bce, float& ps) {
    float e = __expf(-fabsf(s));
    float pa = __fdividef(1.0f, 1.0f + e);      // sigmoid(|s|)
    bce += fmaxf(s, 0.0f) - __logf(pa);          // max(s,0)+log1p(e^-|s|)
    ps += (s >= 0.0f) ? pa : (1.0f - pa);
}

// Blocks [0, AB): assignment, one WARP per (image,gt).
// Blocks [AB, gridDim): dense score reduction (grid-stride).
__global__ __launch_bounds__(256) void k_main(
    const float4* __restrict__ pred_boxes, const float* __restrict__ scores,
    const float2* __restrict__ anchors, const float4* __restrict__ gts,
    const int* __restrict__ img_p, int B, int N, int G, int BG, int AB, int total)
{
    int t = threadIdx.x;
    int lane = t & 31, wid = t >> 5;

    if ((int)blockIdx.x >= AB) {
        // ---------------- score role ----------------
        int sb = blockIdx.x - AB;
        int SBn = gridDim.x - AB;
        int nv4 = total >> 2;
        float bce = 0.0f, ps = 0.0f;
        for (int i = sb * 256 + t; i < nv4; i += SBn * 256) {
            float4 s4 = ((const float4*)scores)[i];
            score_terms(s4.x, bce, ps);
            score_terms(s4.y, bce, ps);
            score_terms(s4.z, bce, ps);
            score_terms(s4.w, bce, ps);
        }
        int tail = total & 3;
        if (sb == 0 && t < tail) score_terms(scores[total - tail + t], bce, ps);

        __shared__ float r0[8], r1[8];
#pragma unroll
        for (int off = 16; off > 0; off >>= 1) {
            bce += __shfl_down_sync(0xFFFFFFFFu, bce, off);
            ps  += __shfl_down_sync(0xFFFFFFFFu, ps, off);
        }
        if (lane == 0) { r0[wid] = bce; r1[wid] = ps; }
        __syncthreads();
        if (t == 0) {
            float a = 0.0f, p = 0.0f;
            for (int w = 0; w < 8; w++) { a += r0[w]; p += r1[w]; }
            atomicAdd(&g_acc[0], (double)a);
            atomicAdd(&g_acc[3], (double)p);
        }
        return;
    }

    // ---------------- assign role: one warp per (b,g) ----------------
    int bg = blockIdx.x * 8 + wid;
    if (bg >= BG) return;
    int b = bg / G, g = bg % G;
    float4 gt = gts[bg];

    u64 v[TOPK];
#pragma unroll
    for (int j = 0; j < TOPK; j++) v[j] = 0ULL;

    const float4* pb_b = pred_boxes + (size_t)b * N;
    const float*  sc_b = scores + (size_t)b * N;

    int img = img_p[0];
    int n0 = img / 8, n1 = img / 16, n2 = img / 32;
    bool structured = (n0 * n0 + n1 * n1 + n2 * n2 == N) && img > 0;

    if (structured) {
        int nn0[3] = {n0, n1, n2};
        int bb0[3] = {0, n0 * n0, n0 * n0 + n1 * n1};
#pragma unroll
        for (int sc = 0; sc < 3; sc++) {
            float s = (float)(8 << sc);
            int n = nn0[sc];
            int cl = max((int)floorf(gt.x / s - 0.5f) - 1, 0);
            int ch = min((int)ceilf(gt.z / s - 0.5f) + 1, n - 1);
            int rl = max((int)floorf(gt.y / s - 0.5f) - 1, 0);
            int rh = min((int)ceilf(gt.w / s - 0.5f) + 1, n - 1);
            int cw = ch - cl + 1, rw = rh - rl + 1;
            if (cw <= 0 || rw <= 0) continue;
            int m = cw * rw;
            for (int k = lane; k < m; k += 32) {
                int row = k / cw + rl;
                int col = k - (k / cw) * cw + cl;
                int a = bb0[sc] + row * n + col;
                float2 an = anchors[a];
                if (an.x >= gt.x && an.x <= gt.z && an.y >= gt.y && an.y <= gt.w) {
                    float4 pb = pb_b[a];
                    float iou = iou_fn(pb, gt);
                    float sv = sc_b[a];
                    float prob = __fdividef(1.0f, 1.0f + __expf(-sv));
                    float i2 = iou * iou;
                    float align = prob * (i2 * i2 * i2);
                    u64 key = ((u64)__float_as_uint(align) << 32)
                            | (u64)(0xFFFFFFFFu - (unsigned)a);
                    if (key > v[TOPK - 1]) {
#pragma unroll
                        for (int j = 0; j < TOPK; j++)
                            if (key > v[j]) { u64 tv = v[j]; v[j] = key; key = tv; }
                    }
                }
            }
        }
    } else {
        for (int a = lane; a < N; a += 32) {
            float2 an = anchors[a];
            if (an.x >= gt.x && an.x <= gt.z && an.y >= gt.y && an.y <= gt.w) {
                float4 pb = pb_b[a];
                float iou = iou_fn(pb, gt);
                float sv = sc_b[a];
                float prob = __fdividef(1.0f, 1.0f + __expf(-sv));
                float i2 = iou * iou;
                float align = prob * (i2 * i2 * i2);
                u64 key = ((u64)__float_as_uint(align) << 32)
                        | (u64)(0xFFFFFFFFu - (unsigned)a);
                if (key > v[TOPK - 1]) {
#pragma unroll
                    for (int j = 0; j < TOPK; j++)
                        if (key > v[j]) { u64 tv = v[j]; v[j] = key; key = tv; }
                }
            }
        }
    }

    // warp top-13 merge: 13 rounds of argmax-of-heads (keys unique)
    u64 myw = 0ULL;
    int ptr = 0;
    for (int r = 0; r < TOPK; r++) {
        u64 h = (ptr < TOPK) ? v[ptr] : 0ULL;
        int src = lane;
#pragma unroll
        for (int off = 16; off > 0; off >>= 1) {
            u64 o = __shfl_down_sync(0xFFFFFFFFu, h, off);
            int os = __shfl_down_sync(0xFFFFFFFFu, src, off);
            if (o > h) { h = o; src = os; }
        }
        u64 hb = __shfl_sync(0xFFFFFFFFu, h, 0);
        int sb_ = __shfl_sync(0xFFFFFFFFu, src, 0);
        if (hb == 0ULL) break;
        if (lane == sb_) ptr++;
        if (lane == r) myw = hb;
    }

    if (lane < TOPK && myw != 0ULL) {
        unsigned bits = (unsigned)(myw >> 32);
        int a = (int)(0xFFFFFFFFu - (unsigned)(myw & 0xFFFFFFFFull));
        u64 key = ((u64)(bits + 1u) << 32) | (u64)(0xFFFFFFFFu - (unsigned)g);
        atomicMax(&g_key[(size_t)b * N + a], key);
        int pos = atomicAdd(&g_cnt, 1);
        if (pos < MAX_LIST) g_list[pos] = make_int2(b * N + a, g);
    }
}

// Foreground terms over compacted list; winner zeroes its key;
// last block (one fence per block, by t0) finalizes and resets state.
__global__ __launch_bounds__(256) void k_fg(
    const float4* __restrict__ pred_boxes, const float* __restrict__ scores,
    const float2* __restrict__ anchors, const float* __restrict__ strides,
    const float* __restrict__ logits, const float* __restrict__ prompt,
    const float4* __restrict__ gts, const int* __restrict__ img_p,
    float* __restrict__ out, int B, int N, int G, int P)
{
    __shared__ double acc_s[MAX_B * 8];
    int t = threadIdx.x;
    for (int i = t; i < B * 8; i += 256) acc_s[i] = 0.0;
    __syncthreads();

    int i = blockIdx.x * 256 + t;
    int cnt = g_cnt;
    if (cnt > MAX_LIST) cnt = MAX_LIST;
    if (i < cnt) {
        int2 e = g_list[i];
        int idx = e.x, g = e.y;
        int b = idx / N, a = idx - b * N;
        u64 key = g_key[idx];
        int gw = (int)(0xFFFFFFFFu - (unsigned)(key & 0xFFFFFFFFull));
        if (key != 0ULL && gw == g) {
            g_key[idx] = 0ULL;   // winner cleans up (one winner per key)
            float4 gt = gts[b * G + g];
            float4 pb = pred_boxes[idx];
            float s = scores[idx];
            float prob = 1.0f / (1.0f + expf(-s));
            float iou = iou_fn(pb, gt);
            float ts = fmaxf(iou, 0.1f);
            float cw = fmaxf(pb.z, gt.z) - fminf(pb.x, gt.x);
            float ch = fmaxf(pb.w, gt.w) - fminf(pb.y, gt.y);
            float c2 = cw * cw + ch * ch + EPSF;
            float dx = gt.x + gt.z - pb.x - pb.z;
            float dy = gt.y + gt.w - pb.y - pb.w;
            float rho2 = (dx * dx + dy * dy) * 0.25f;
            float w1 = pb.z - pb.x, h1 = pb.w - pb.y + EPSF;
            float w2 = gt.z - gt.x, h2 = gt.w - gt.y + EPSF;
            float dat = atanf(w2 / h2) - atanf(w1 / h1);
            float vv = 0.40528473456935109f * dat * dat;
            float alpha = vv / (vv - iou + 1.0f + EPSF);
            float ciou = iou - rho2 / c2 - vv * alpha;
            float2 an = anchors[a];
            float st = strides[a];
            float dist[4];
            dist[0] = (an.x - gt.x) / st;
            dist[1] = (an.y - gt.y) / st;
            dist[2] = (gt.z - an.x) / st;
            dist[3] = (gt.w - an.y) / st;
            const float* lg = logits + (size_t)idx * 64;
            float dflv = 0.0f;
#pragma unroll
            for (int ch_i = 0; ch_i < 4; ch_i++) {
                float x[16];
                const float4* l4 = (const float4*)(lg + ch_i * 16);
#pragma unroll
                for (int q = 0; q < 4; q++) {
                    float4 f = l4[q];
                    x[q * 4 + 0] = f.x; x[q * 4 + 1] = f.y;
                    x[q * 4 + 2] = f.z; x[q * 4 + 3] = f.w;
                }
                float m = x[0];
#pragma unroll
                for (int q = 1; q < 16; q++) m = fmaxf(m, x[q]);
                float se = 0.0f;
#pragma unroll
                for (int q = 0; q < 16; q++) se += __expf(x[q] - m);
                float logZ = m + __logf(se);
                float d = fminf(fmaxf(dist[ch_i], 0.0f), 16.0f - 1.0f - 0.01f);
                int tl = (int)d;
                int tr = min(tl + 1, 15);
                float wl = (float)tr - d;
                float wr = 1.0f - wl;
                dflv += (logZ - x[tl]) * wl + (logZ - x[tr]) * wr;
            }
            float img = fmaxf((float)img_p[0], 1.0f);
            float cx = (gt.x + gt.z) * 0.5f / img;
            float cy = (gt.y + gt.w) * 0.5f / img;
            float cn = fmaxf(sqrtf(cx * cx + cy * cy), 1e-12f);
            cx /= cn; cy /= cn;
            float p0 = prompt[(size_t)b * P + 0], p1 = prompt[(size_t)b * P + 1];
            float pn = fmaxf(sqrtf(p0 * p0 + p1 * p1), 1e-12f);
            float ctr = 1.0f - (cx * p0 + cy * p1) / pn;

            double* A = acc_s + b * 8;
            atomicAdd(&A[0], (double)(-s * ts));
            atomicAdd(&A[1], 1.0);
            atomicAdd(&A[2], (double)prob);
            atomicAdd(&A[4], (double)iou);
            atomicAdd(&A[5], (double)(1.0f - ciou));
            atomicAdd(&A[6], (double)dflv);
            atomicAdd(&A[7], (double)ctr);
        }
    }
    __syncthreads();
    for (int j = t; j < B * 8; j += 256) {
        double val = acc_s[j];
        if (val != 0.0) atomicAdd(&g_acc[j], val);
    }
    __syncthreads();

    __shared__ int s_last;
    if (t == 0) {
        __threadfence();                       // one fence per block
        s_last = (atomicAdd(&g_done, 1) == (int)gridDim.x - 1);
    }
    __syncthreads();
    if (!s_last) return;

    // ---- last block: finalize + reset ----
    __shared__ double pm[MAX_B], pi[MAX_B], pdf[MAX_B], pc[MAX_B];
    __shared__ double pt[MAX_B], pp[MAX_B], ptot[MAX_B], pmi[MAX_B];
    if (t < B) {
        const double* A = &g_acc[t * 8];
        double np = A[1];
        double den = fmax(np, 1.0);
        pm[t] = A[0] / (double)N;
        pt[t] = np;
        pp[t] = A[2];
        ptot[t] = A[3];
        pmi[t] = A[4];
        pi[t] = A[5] / den;
        pdf[t] = A[6] / (4.0 * den);
        pc[t] = A[7] / den;
    }
    __syncthreads();
    if (t == 0) {
        double match = 0, iou = 0, dfl = 0, ctr = 0, tp = 0, pos = 0, tot = 0, mi = 0;
        for (int b = 0; b < B; b++) {
            match += pm[b]; iou += pi[b]; dfl += pdf[b]; ctr += pc[b];
            tp += pt[b]; pos += pp[b]; tot += ptot[b]; mi += pmi[b];
        }
        double nb_ = (double)B;
        double tneg = (double)B * (double)N - tp;
        out[0] = (float)((1.0 * match + 7.5 * iou + 1.5 * dfl + 1.0 * ctr) / nb_);
        out[1] = (float)(match / nb_);
        out[2] = (float)(iou / nb_);
        out[3] = (float)(dfl / nb_);
        out[4] = (float)(ctr / nb_);
        out[5] = (float)tp;
        out[6] = (float)tneg;
        out[7] = (float)(pos / fmax(tp, 1.0));
        out[8] = (float)((tot - pos) / fmax(tneg, 1.0));
        out[9] = (float)(mi / fmax(tp, 1.0));
        g_cnt = 0;
        g_done = 0;
    }
    __syncthreads();
    for (int j = t; j < B * 8; j += 256) g_acc[j] = 0.0;
}

extern "C" void kernel_launch(void* const* d_in, const int* in_sizes, int n_in,
                              void* d_out, int out_size) {
    const float* pred_boxes = (const float*)d_in[0];
    const float* pred_scores = (const float*)d_in[1];
    const float* anchors = (const float*)d_in[2];
    const float* strides = (const float*)d_in[3];
    const float* logits = (const float*)d_in[4];
    const float* prompt = (const float*)d_in[5];
    const float* gts = (const float*)d_in[6];
    const int* imgp = (const int*)d_in[7];

    int N = in_sizes[2] / 2;
    int B = in_sizes[1] / N;
    int G = in_sizes[6] / (4 * B);
    int P = in_sizes[5] / B;
    int BG = B * G;
    int total = B * N;
    int AB = (BG + 7) / 8;          // assign blocks (8 warps = 8 (b,g) rows each)
    int SB = 296;                   // score blocks (grid-stride)

    k_main<<<AB + SB, 256>>>((const float4*)pred_boxes, pred_scores,
                             (const float2*)anchors, (const float4*)gts,
                             imgp, B, N, G, BG, AB, total);
    int cap = BG * TOPK;
    if (cap > MAX_LIST) cap = MAX_LIST;
    k_fg<<<(cap + 255) / 256, 256>>>((const float4*)pred_boxes, pred_scores,
                                     (const float2*)anchors, strides, logits, prompt,
                                     (const float4*)gts, imgp, (float*)d_out,
                                     B, N, G, P);
}

// round 7
// speedup vs baseline: 1.8062x; 1.7284x over previous
#include <cuda_runtime.h>
#include <math.h>

#define TOPK 13
#define EPSF 1e-7f
#define MAX_BN (1 << 20)
#define MAX_B 64
#define MAX_LIST 16384
#define FINAL_BLOCKS 32
#define FG_THREADS 64

typedef unsigned long long u64;

__device__ u64 g_key[MAX_BN];
__device__ double g_acc[MAX_B * 8];
__device__ int g_cnt;
__device__ int g_cnt2;
__device__ int2 g_list[MAX_LIST];

__device__ __forceinline__ float iou_fn(float4 a, float4 b) {
    float x1 = fmaxf(a.x, b.x), y1 = fmaxf(a.y, b.y);
    float x2 = fminf(a.z, b.z), y2 = fminf(a.w, b.w);
    float inter = fmaxf(x2 - x1, 0.0f) * fmaxf(y2 - y1, 0.0f);
    float aa = (a.z - a.x) * (a.w - a.y);
    float ab = (b.z - b.x) * (b.w - b.y);
    return inter / (aa + ab - inter + EPSF);
}

// Fused kernel: blocks [0, BG) do assignment (one per image,gt);
// blocks [BG, BG+scoreBlocks) do the dense score reduction.
__global__ __launch_bounds__(256) void k_main(
    const float4* __restrict__ pred_boxes, const float* __restrict__ scores,
    const float2* __restrict__ anchors, const float4* __restrict__ gts,
    const int* __restrict__ img_p, int B, int N, int G, int BG, int total)
{
    int t = threadIdx.x;

    if ((int)blockIdx.x >= BG) {
        // ---------------- score role: flat over B*N ----------------
        int sb = blockIdx.x - BG;
        int i0 = (sb * 256 + t) * 8;
        float bce = 0.0f, ps = 0.0f;
#pragma unroll
        for (int q = 0; q < 2; q++) {
            int base = i0 + q * 4;
            float sv[4];
            bool full = (base + 3 < total);
            if (full) {
                float4 s4 = *(const float4*)(scores + base);
                sv[0] = s4.x; sv[1] = s4.y; sv[2] = s4.z; sv[3] = s4.w;
            }
#pragma unroll
            for (int j = 0; j < 4; j++) {
                float s;
                bool valid = full;
                if (full) s = sv[j];
                else { int i = base + j; valid = (i < total); s = valid ? scores[i] : 0.0f; }
                if (valid) {
                    float e = __expf(-fabsf(s));
                    float pa = 1.0f / (1.0f + e);          // sigmoid(|s|)
                    bce += fmaxf(s, 0.0f) - __logf(pa);    // max(s,0)+log1p(e^-|s|)
                    ps += (s >= 0.0f) ? pa : 1.0f - pa;
                }
            }
        }
        __shared__ float r0[8], r1[8];
        int lane = t & 31, wid = t >> 5;
#pragma unroll
        for (int off = 16; off > 0; off >>= 1) {
            bce += __shfl_down_sync(0xFFFFFFFFu, bce, off);
            ps  += __shfl_down_sync(0xFFFFFFFFu, ps, off);
        }
        if (lane == 0) { r0[wid] = bce; r1[wid] = ps; }
        __syncthreads();
        if (t == 0) {
            float a = 0.0f, p = 0.0f;
            for (int w = 0; w < 8; w++) { a += r0[w]; p += r1[w]; }
            atomicAdd(&g_acc[0], (double)a);   // global bce0
            atomicAdd(&g_acc[3], (double)p);   // global prob sum
        }
        return;
    }

    // ---------------- assign role ----------------
    int bg = blockIdx.x;
    int b = bg / G, g = bg % G;
    float4 gt = gts[bg];

    u64 v[TOPK];
#pragma unroll
    for (int j = 0; j < TOPK; j++) v[j] = 0ULL;

    const float4* pb_b = pred_boxes + (size_t)b * N;
    const float*  sc_b = scores + (size_t)b * N;

    int img = img_p[0];
    int n0 = img / 8, n1 = img / 16, n2 = img / 32;
    bool structured = (n0 * n0 + n1 * n1 + n2 * n2 == N) && img > 0;

    if (structured) {
        int nn[3] = {n0, n1, n2};
        int base[3] = {0, n0 * n0, n0 * n0 + n1 * n1};
        int c0[3], r0a[3], cw[3], m[3];
        int M = 0;
#pragma unroll
        for (int sc = 0; sc < 3; sc++) {
            float s = (float)(8 << sc);
            int n = nn[sc];
            int cl = (int)floorf(gt.x / s - 0.5f) - 1;
            int ch = (int)ceilf(gt.z / s - 0.5f) + 1;
            int rl = (int)floorf(gt.y / s - 0.5f) - 1;
            int rh = (int)ceilf(gt.w / s - 0.5f) + 1;
            cl = max(cl, 0); ch = min(ch, n - 1);
            rl = max(rl, 0); rh = min(rh, n - 1);
            int ccw = ch - cl + 1, crh = rh - rl + 1;
            if (ccw < 0) ccw = 0;
            if (crh < 0) crh = 0;
            c0[sc] = cl; r0a[sc] = rl; cw[sc] = ccw;
            m[sc] = ccw * crh;
            M += m[sc];
        }
        for (int k = t; k < M; k += 256) {
            int sc = 0, rel = k;
            while (rel >= m[sc]) { rel -= m[sc]; sc++; }
            int row = rel / cw[sc] + r0a[sc];
            int col = rel % cw[sc] + c0[sc];
            int a = base[sc] + row * nn[sc] + col;
            float2 an = anchors[a];
            if (an.x >= gt.x && an.x <= gt.z && an.y >= gt.y && an.y <= gt.w) {
                float4 pb = pb_b[a];
                float iou = iou_fn(pb, gt);
                float s = sc_b[a];
                float prob = 1.0f / (1.0f + __expf(-s));
                float i2 = iou * iou;
                float align = prob * (i2 * i2 * i2);
                u64 key = ((u64)__float_as_uint(align) << 32)
                        | (u64)(0xFFFFFFFFu - (unsigned)a);
                if (key > v[TOPK - 1]) {
#pragma unroll
                    for (int j = 0; j < TOPK; j++)
                        if (key > v[j]) { u64 tv = v[j]; v[j] = key; key = tv; }
                }
            }
        }
    } else {
        for (int a = t; a < N; a += 256) {
            float2 an = anchors[a];
            if (an.x >= gt.x && an.x <= gt.z && an.y >= gt.y && an.y <= gt.w) {
                float4 pb = pb_b[a];
                float iou = iou_fn(pb, gt);
                float s = sc_b[a];
                float prob = 1.0f / (1.0f + __expf(-s));
                float i2 = iou * iou;
                float align = prob * (i2 * i2 * i2);
                u64 key = ((u64)__float_as_uint(align) << 32)
                        | (u64)(0xFFFFFFFFu - (unsigned)a);
                if (key > v[TOPK - 1]) {
#pragma unroll
                    for (int j = 0; j < TOPK; j++)
                        if (key > v[j]) { u64 tv = v[j]; v[j] = key; key = tv; }
                }
            }
        }
    }

    // block-wide top-13 merge (head-pointer rounds on packed u64; keys unique)
    __shared__ u64 s_v[8]; __shared__ int s_t[8];
    __shared__ u64 s_w[TOPK];
    __shared__ int w_t; __shared__ int s_done;
    if (t == 0) s_done = 0;
    if (t < TOPK) s_w[t] = 0ULL;
    int ptr = 0;
    int lane = t & 31, wid = t >> 5;
    __syncthreads();

    for (int round = 0; round < TOPK; round++) {
        u64 hv = (ptr < TOPK) ? v[ptr] : 0ULL;
        int ht = t;
#pragma unroll
        for (int off = 16; off > 0; off >>= 1) {
            u64 ov = __shfl_down_sync(0xFFFFFFFFu, hv, off);
            int ot = __shfl_down_sync(0xFFFFFFFFu, ht, off);
            if (ov > hv) { hv = ov; ht = ot; }
        }
        if (lane == 0) { s_v[wid] = hv; s_t[wid] = ht; }
        __syncthreads();
        if (t == 0) {
            u64 bv = s_v[0]; int bt = s_t[0];
            for (int w = 1; w < 8; w++)
                if (s_v[w] > bv) { bv = s_v[w]; bt = s_t[w]; }
            if (bv == 0ULL) s_done = 1;
            else { s_w[round] = bv; w_t = bt; }
        }
        __syncthreads();
        if (s_done) break;
        if (t == w_t) ptr++;
    }
    __syncthreads();

    if (t < TOPK) {
        u64 w = s_w[t];
        if (w != 0ULL) {
            unsigned bits = (unsigned)(w >> 32);
            int a = (int)(0xFFFFFFFFu - (unsigned)(w & 0xFFFFFFFFull));
            u64 key = ((u64)(bits + 1u) << 32)
                    | (u64)(0xFFFFFFFFu - (unsigned)g);
            atomicMax(&g_key[(size_t)b * N + a], key);
            int pos = atomicAdd(&g_cnt, 1);
            if (pos < MAX_LIST) g_list[pos] = make_int2(b * N + a, g);
        }
    }
}

// Foreground terms: 64-thread blocks, one entry per thread, 65 blocks
// so the ~70 MUFU/entry spread over ~65 SMs instead of 17.
__global__ __launch_bounds__(FG_THREADS) void k_fg(
    const float4* __restrict__ pred_boxes, const float* __restrict__ scores,
    const float2* __restrict__ anchors, const float* __restrict__ strides,
    const float* __restrict__ logits, const float* __restrict__ prompt,
    const float4* __restrict__ gts, const int* __restrict__ img_p,
    int B, int N, int G, int P)
{
    __shared__ double acc_s[MAX_B * 8];
    int t = threadIdx.x;
    if (blockIdx.x == 0 && t == 0) {
        int c = g_cnt;
        g_cnt2 = c < MAX_LIST ? c : MAX_LIST;
    }
    for (int i = t; i < B * 8; i += FG_THREADS) acc_s[i] = 0.0;
    __syncthreads();

    int i = blockIdx.x * FG_THREADS + t;
    int cnt = g_cnt;
    if (cnt > MAX_LIST) cnt = MAX_LIST;
    if (i < cnt) {
        int2 e = g_list[i];
        int idx = e.x, g = e.y;
        int b = idx / N, a = idx - b * N;
        u64 key = g_key[idx];
        int gw = (int)(0xFFFFFFFFu - (unsigned)(key & 0xFFFFFFFFull));
        if (gw == g) {
            float4 gt = gts[b * G + g];
            float4 pb = pred_boxes[idx];
            float s = scores[idx];
            float prob = 1.0f / (1.0f + expf(-s));
            float iou = iou_fn(pb, gt);
            float ts = fmaxf(iou, 0.1f);
            float cw = fmaxf(pb.z, gt.z) - fminf(pb.x, gt.x);
            float ch = fmaxf(pb.w, gt.w) - fminf(pb.y, gt.y);
            float c2 = cw * cw + ch * ch + EPSF;
            float dx = gt.x + gt.z - pb.x - pb.z;
            float dy = gt.y + gt.w - pb.y - pb.w;
            float rho2 = (dx * dx + dy * dy) * 0.25f;
            float w1 = pb.z - pb.x, h1 = pb.w - pb.y + EPSF;
            float w2 = gt.z - gt.x, h2 = gt.w - gt.y + EPSF;
            float dat = atanf(w2 / h2) - atanf(w1 / h1);
            float vv = 0.40528473456935109f * dat * dat;
            float alpha = vv / (vv - iou + 1.0f + EPSF);
            float ciou = iou - rho2 / c2 - vv * alpha;
            float2 an = anchors[a];
            float st = strides[a];
            float dist[4];
            dist[0] = (an.x - gt.x) / st;
            dist[1] = (an.y - gt.y) / st;
            dist[2] = (gt.z - an.x) / st;
            dist[3] = (gt.w - an.y) / st;
            const float* lg = logits + (size_t)idx * 64;
            float dflv = 0.0f;
#pragma unroll
            for (int ch_i = 0; ch_i < 4; ch_i++) {
                float x[16];
                const float4* l4 = (const float4*)(lg + ch_i * 16);
#pragma unroll
                for (int q = 0; q < 4; q++) {
                    float4 f = l4[q];
                    x[q * 4 + 0] = f.x; x[q * 4 + 1] = f.y;
                    x[q * 4 + 2] = f.z; x[q * 4 + 3] = f.w;
                }
                float m = x[0];
#pragma unroll
                for (int q = 1; q < 16; q++) m = fmaxf(m, x[q]);
                float se = 0.0f;
#pragma unroll
                for (int q = 0; q < 16; q++) se += __expf(x[q] - m);
                float logZ = m + __logf(se);
                float d = fminf(fmaxf(dist[ch_i], 0.0f), 16.0f - 1.0f - 0.01f);
                int tl = (int)d;
                int tr = min(tl + 1, 15);
                float wl = (float)tr - d;
                float wr = 1.0f - wl;
                dflv += (logZ - x[tl]) * wl + (logZ - x[tr]) * wr;
            }
            float img = fmaxf((float)img_p[0], 1.0f);
            float cx = (gt.x + gt.z) * 0.5f / img;
            float cy = (gt.y + gt.w) * 0.5f / img;
            float cn = fmaxf(sqrtf(cx * cx + cy * cy), 1e-12f);
            cx /= cn; cy /= cn;
            float p0 = prompt[(size_t)b * P + 0], p1 = prompt[(size_t)b * P + 1];
            float pn = fmaxf(sqrtf(p0 * p0 + p1 * p1), 1e-12f);
            float ctr = 1.0f - (cx * p0 + cy * p1) / pn;

            double* A = acc_s + b * 8;
            atomicAdd(&A[0], (double)(-s * ts));
            atomicAdd(&A[1], 1.0);
            atomicAdd(&A[2], (double)prob);
            atomicAdd(&A[4], (double)iou);
            atomicAdd(&A[5], (double)(1.0f - ciou));
            atomicAdd(&A[6], (double)dflv);
            atomicAdd(&A[7], (double)ctr);
        }
    }
    __syncthreads();
    for (int j = t; j < B * 8; j += FG_THREADS) {
        double val = acc_s[j];
        if (val != 0.0) atomicAdd(&g_acc[j], val);
    }
}

// Multi-block: cleanup keys (all blocks, via g_cnt2 snapshot); block 0 finalizes.
__global__ __launch_bounds__(256) void k_final(float* __restrict__ out, int B, int N) {
    int t = threadIdx.x;
    int cnt = g_cnt2;
    if (cnt > MAX_LIST) cnt = MAX_LIST;
    for (int i = blockIdx.x * 256 + t; i < cnt; i += FINAL_BLOCKS * 256)
        g_key[g_list[i].x] = 0ULL;
    if (blockIdx.x != 0) return;

    __shared__ double pm[MAX_B], pi[MAX_B], pdf[MAX_B], pc[MAX_B];
    __shared__ double pt[MAX_B], pp[MAX_B], ptot[MAX_B], pmi[MAX_B];
    if (t < B) {
        const double* A = &g_acc[t * 8];
        double np = A[1];
        double den = fmax(np, 1.0);
        pm[t] = A[0] / (double)N;
        pt[t] = np;
        pp[t] = A[2];
        ptot[t] = A[3];
        pmi[t] = A[4];
        pi[t] = A[5] / den;
        pdf[t] = A[6] / (4.0 * den);
        pc[t] = A[7] / den;
    }
    __syncthreads();
    if (t == 0) {
        double match = 0, iou = 0, dfl = 0, ctr = 0, tp = 0, pos = 0, tot = 0, mi = 0;
        for (int b = 0; b < B; b++) {
            match += pm[b]; iou += pi[b]; dfl += pdf[b]; ctr += pc[b];
            tp += pt[b]; pos += pp[b]; tot += ptot[b]; mi += pmi[b];
        }
        double nb = (double)B;
        double tneg = (double)B * (double)N - tp;
        out[0] = (float)((1.0 * match + 7.5 * iou + 1.5 * dfl + 1.0 * ctr) / nb);
        out[1] = (float)(match / nb);
        out[2] = (float)(iou / nb);
        out[3] = (float)(dfl / nb);
        out[4] = (float)(ctr / nb);
        out[5] = (float)tp;
        out[6] = (float)tneg;
        out[7] = (float)(pos / fmax(tp, 1.0));
        out[8] = (float)((tot - pos) / fmax(tneg, 1.0));
        out[9] = (float)(mi / fmax(tp, 1.0));
        g_cnt = 0;
    }
    __syncthreads();
    for (int j = t; j < B * 8; j += 256) g_acc[j] = 0.0;
}

extern "C" void kernel_launch(void* const* d_in, const int* in_sizes, int n_in,
                              void* d_out, int out_size) {
    const float* pred_boxes = (const float*)d_in[0];
    const float* pred_scores = (const float*)d_in[1];
    const float* anchors = (const float*)d_in[2];
    const float* strides = (const float*)d_in[3];
    const float* logits = (const float*)d_in[4];
    const float* prompt = (const float*)d_in[5];
    const float* gts = (const float*)d_in[6];
    const int* imgp = (const int*)d_in[7];

    int N = in_sizes[2] / 2;
    int B = in_sizes[1] / N;
    int G = in_sizes[6] / (4 * B);
    int P = in_sizes[5] / B;
    int BG = B * G;
    int total = B * N;
    int scoreBlocks = (total + 2047) / 2048;

    k_main<<<BG + scoreBlocks, 256>>>((const float4*)pred_boxes, pred_scores,
                                      (const float2*)anchors, (const float4*)gts,
                                      imgp, B, N, G, BG, total);
    int cap = BG * TOPK;
    if (cap > MAX_LIST) cap = MAX_LIST;
    k_fg<<<(cap + FG_THREADS - 1) / FG_THREADS, FG_THREADS>>>(
        (const float4*)pred_boxes, pred_scores,
        (const float2*)anchors, strides, logits, prompt,
        (const float4*)gts, imgp, B, N, G, P);
    k_final<<<FINAL_BLOCKS, 256>>>((float*)d_out, B, N);
}

// round 8
// speedup vs baseline: 1.8145x; 1.0046x over previous
#include <cuda_runtime.h>
#include <math.h>

#define TOPK 13
#define EPSF 1e-7f
#define MAX_BN (1 << 20)
#define MAX_B 64
#define MAX_LIST 16384
#define FG_THREADS 64

typedef unsigned long long u64;

__device__ u64 g_key[MAX_BN];
__device__ double g_acc[MAX_B * 8];
__device__ int g_cnt;
__device__ int g_done;
__device__ int2 g_list[MAX_LIST];

__device__ __forceinline__ float iou_fn(float4 a, float4 b) {
    float x1 = fmaxf(a.x, b.x), y1 = fmaxf(a.y, b.y);
    float x2 = fminf(a.z, b.z), y2 = fminf(a.w, b.w);
    float inter = fmaxf(x2 - x1, 0.0f) * fmaxf(y2 - y1, 0.0f);
    float aa = (a.z - a.x) * (a.w - a.y);
    float ab = (b.z - b.x) * (b.w - b.y);
    return inter / (aa + ab - inter + EPSF);
}

// Fused: blocks [0, BG) assignment (one block per (image,gt));
// blocks [BG, ...) dense score reduction.
__global__ __launch_bounds__(256) void k_main(
    const float4* __restrict__ pred_boxes, const float* __restrict__ scores,
    const float2* __restrict__ anchors, const float4* __restrict__ gts,
    const int* __restrict__ img_p, int B, int N, int G, int BG, int total)
{
    int t = threadIdx.x;
    int lane = t & 31, wid = t >> 5;

    if ((int)blockIdx.x >= BG) {
        // ---------------- score role ----------------
        int sb = blockIdx.x - BG;
        int i0 = (sb * 256 + t) * 8;
        float bce = 0.0f, ps = 0.0f;
#pragma unroll
        for (int q = 0; q < 2; q++) {
            int base = i0 + q * 4;
            float sv[4];
            bool full = (base + 3 < total);
            if (full) {
                float4 s4 = *(const float4*)(scores + base);
                sv[0] = s4.x; sv[1] = s4.y; sv[2] = s4.z; sv[3] = s4.w;
            }
#pragma unroll
            for (int j = 0; j < 4; j++) {
                float s;
                bool valid = full;
                if (full) s = sv[j];
                else { int i = base + j; valid = (i < total); s = valid ? scores[i] : 0.0f; }
                if (valid) {
                    float e = __expf(-fabsf(s));
                    float pa = 1.0f / (1.0f + e);          // sigmoid(|s|)
                    bce += fmaxf(s, 0.0f) - __logf(pa);    // max(s,0)+log1p(e^-|s|)
                    ps += (s >= 0.0f) ? pa : 1.0f - pa;
                }
            }
        }
        __shared__ float r0[8], r1[8];
#pragma unroll
        for (int off = 16; off > 0; off >>= 1) {
            bce += __shfl_down_sync(0xFFFFFFFFu, bce, off);
            ps  += __shfl_down_sync(0xFFFFFFFFu, ps, off);
        }
        if (lane == 0) { r0[wid] = bce; r1[wid] = ps; }
        __syncthreads();
        if (t == 0) {
            float a = 0.0f, p = 0.0f;
            for (int w = 0; w < 8; w++) { a += r0[w]; p += r1[w]; }
            atomicAdd(&g_acc[0], (double)a);   // global bce0
            atomicAdd(&g_acc[3], (double)p);   // global prob sum
        }
        return;
    }

    // ---------------- assign role ----------------
    int bg = blockIdx.x;
    int b = bg / G, g = bg % G;
    float4 gt = gts[bg];

    u64 v[TOPK];
#pragma unroll
    for (int j = 0; j < TOPK; j++) v[j] = 0ULL;

    const float4* pb_b = pred_boxes + (size_t)b * N;
    const float*  sc_b = scores + (size_t)b * N;

    int img = img_p[0];
    int n0 = img / 8, n1 = img / 16, n2 = img / 32;
    bool structured = (n0 * n0 + n1 * n1 + n2 * n2 == N) && img > 0;

    if (structured) {
        int nn[3] = {n0, n1, n2};
        int base[3] = {0, n0 * n0, n0 * n0 + n1 * n1};
        int c0[3], r0a[3], cw[3], m[3];
        int M = 0;
#pragma unroll
        for (int sc = 0; sc < 3; sc++) {
            float s = (float)(8 << sc);
            int n = nn[sc];
            int cl = max((int)floorf(gt.x / s - 0.5f) - 1, 0);
            int ch = min((int)ceilf(gt.z / s - 0.5f) + 1, n - 1);
            int rl = max((int)floorf(gt.y / s - 0.5f) - 1, 0);
            int rh = min((int)ceilf(gt.w / s - 0.5f) + 1, n - 1);
            int ccw = ch - cl + 1, crh = rh - rl + 1;
            if (ccw < 0) ccw = 0;
            if (crh < 0) crh = 0;
            c0[sc] = cl; r0a[sc] = rl; cw[sc] = ccw;
            m[sc] = ccw * crh;
            M += m[sc];
        }
        for (int k = t; k < M; k += 256) {
            int sc = 0, rel = k;
            while (rel >= m[sc]) { rel -= m[sc]; sc++; }
            int row = rel / cw[sc] + r0a[sc];
            int col = rel % cw[sc] + c0[sc];
            int a = base[sc] + row * nn[sc] + col;
            float2 an = anchors[a];
            if (an.x >= gt.x && an.x <= gt.z && an.y >= gt.y && an.y <= gt.w) {
                float4 pb = pb_b[a];
                float iou = iou_fn(pb, gt);
                float s = sc_b[a];
                float prob = 1.0f / (1.0f + __expf(-s));
                float i2 = iou * iou;
                float align = prob * (i2 * i2 * i2);
                u64 key = ((u64)__float_as_uint(align) << 32)
                        | (u64)(0xFFFFFFFFu - (unsigned)a);
                if (key > v[TOPK - 1]) {
#pragma unroll
                    for (int j = 0; j < TOPK; j++)
                        if (key > v[j]) { u64 tv = v[j]; v[j] = key; key = tv; }
                }
            }
        }
    } else {
        for (int a = t; a < N; a += 256) {
            float2 an = anchors[a];
            if (an.x >= gt.x && an.x <= gt.z && an.y >= gt.y && an.y <= gt.w) {
                float4 pb = pb_b[a];
                float iou = iou_fn(pb, gt);
                float s = sc_b[a];
                float prob = 1.0f / (1.0f + __expf(-s));
                float i2 = iou * iou;
                float align = prob * (i2 * i2 * i2);
                u64 key = ((u64)__float_as_uint(align) << 32)
                        | (u64)(0xFFFFFFFFu - (unsigned)a);
                if (key > v[TOPK - 1]) {
#pragma unroll
                    for (int j = 0; j < TOPK; j++)
                        if (key > v[j]) { u64 tv = v[j]; v[j] = key; key = tv; }
                }
            }
        }
    }

    // ---- level 1: per-warp top-13 (no block syncs) ----
    __shared__ u64 s_all[8 * TOPK];
    {
        u64 myw = 0ULL;
        int ptr = 0;
        for (int r = 0; r < TOPK; r++) {
            u64 h = (ptr < TOPK) ? v[ptr] : 0ULL;
            int src = lane;
#pragma unroll
            for (int off = 16; off > 0; off >>= 1) {
                u64 o = __shfl_down_sync(0xFFFFFFFFu, h, off);
                int os = __shfl_down_sync(0xFFFFFFFFu, src, off);
                if (o > h) { h = o; src = os; }
            }
            u64 hb = __shfl_sync(0xFFFFFFFFu, h, 0);
            int sl = __shfl_sync(0xFFFFFFFFu, src, 0);
            if (hb == 0ULL) break;
            if (lane == sl) ptr++;
            if (lane == r) myw = hb;
        }
        if (lane < TOPK) s_all[wid * TOPK + lane] = myw;   // sorted desc per warp
    }
    __syncthreads();
    if (wid != 0) return;

    // ---- level 2: warp 0 merges 8 sorted lists of 13 ----
    {
        u64 myw = 0ULL;
        int ptr = 0;   // per-lane head pointer (lanes 0..7 own a list)
        for (int r = 0; r < TOPK; r++) {
            u64 h = (lane < 8 && ptr < TOPK) ? s_all[lane * TOPK + ptr] : 0ULL;
            int src = lane;
#pragma unroll
            for (int off = 4; off > 0; off >>= 1) {
                u64 o = __shfl_down_sync(0xFFFFFFFFu, h, off);
                int os = __shfl_down_sync(0xFFFFFFFFu, src, off);
                if (o > h) { h = o; src = os; }
            }
            u64 hb = __shfl_sync(0xFFFFFFFFu, h, 0);
            int sl = __shfl_sync(0xFFFFFFFFu, src, 0);
            if (hb == 0ULL) break;
            if (lane == sl) ptr++;
            if (lane == r) myw = hb;
        }
        if (lane < TOPK && myw != 0ULL) {
            unsigned bits = (unsigned)(myw >> 32);
            int a = (int)(0xFFFFFFFFu - (unsigned)(myw & 0xFFFFFFFFull));
            u64 key = ((u64)(bits + 1u) << 32) | (u64)(0xFFFFFFFFu - (unsigned)g);
            atomicMax(&g_key[(size_t)b * N + a], key);
            int pos = atomicAdd(&g_cnt, 1);
            if (pos < MAX_LIST) g_list[pos] = make_int2(b * N + a, g);
        }
    }
}

// Foreground terms (64-thread blocks, one entry per thread); winner zeroes
// its own key; last block finalizes output and resets state.
__global__ __launch_bounds__(FG_THREADS) void k_fg(
    const float4* __restrict__ pred_boxes, const float* __restrict__ scores,
    const float2* __restrict__ anchors, const float* __restrict__ strides,
    const float* __restrict__ logits, const float* __restrict__ prompt,
    const float4* __restrict__ gts, const int* __restrict__ img_p,
    float* __restrict__ out, int B, int N, int G, int P)
{
    __shared__ double acc_s[MAX_B * 8];
    int t = threadIdx.x;
    for (int i = t; i < B * 8; i += FG_THREADS) acc_s[i] = 0.0;
    __syncthreads();

    int i = blockIdx.x * FG_THREADS + t;
    int cnt = g_cnt;
    if (cnt > MAX_LIST) cnt = MAX_LIST;
    if (i < cnt) {
        int2 e = g_list[i];
        int idx = e.x, g = e.y;
        int b = idx / N, a = idx - b * N;
        u64 key = g_key[idx];
        int gw = (int)(0xFFFFFFFFu - (unsigned)(key & 0xFFFFFFFFull));
        if (key != 0ULL && gw == g) {
            g_key[idx] = 0ULL;    // exactly-once cleanup by the winner
            float4 gt = gts[b * G + g];
            float4 pb = pred_boxes[idx];
            float s = scores[idx];
            float prob = 1.0f / (1.0f + expf(-s));
            float iou = iou_fn(pb, gt);
            float ts = fmaxf(iou, 0.1f);
            float cw = fmaxf(pb.z, gt.z) - fminf(pb.x, gt.x);
            float ch = fmaxf(pb.w, gt.w) - fminf(pb.y, gt.y);
            float c2 = cw * cw + ch * ch + EPSF;
            float dx = gt.x + gt.z - pb.x - pb.z;
            float dy = gt.y + gt.w - pb.y - pb.w;
            float rho2 = (dx * dx + dy * dy) * 0.25f;
            float w1 = pb.z - pb.x, h1 = pb.w - pb.y + EPSF;
            float w2 = gt.z - gt.x, h2 = gt.w - gt.y + EPSF;
            float dat = atanf(w2 / h2) - atanf(w1 / h1);
            float vv = 0.40528473456935109f * dat * dat;
            float alpha = vv / (vv - iou + 1.0f + EPSF);
            float ciou = iou - rho2 / c2 - vv * alpha;
            float2 an = anchors[a];
            float st = strides[a];
            float dist[4];
            dist[0] = (an.x - gt.x) / st;
            dist[1] = (an.y - gt.y) / st;
            dist[2] = (gt.z - an.x) / st;
            dist[3] = (gt.w - an.y) / st;
            const float* lg = logits + (size_t)idx * 64;
            float dflv = 0.0f;
#pragma unroll
        for (int ch_i = 0; ch_i < 4; ch_i++) {
                float x[16];
                const float4* l4 = (const float4*)(lg + ch_i * 16);
#pragma unroll
                for (int q = 0; q < 4; q++) {
                    float4 f = l4[q];
                    x[q * 4 + 0] = f.x; x[q * 4 + 1] = f.y;
                    x[q * 4 + 2] = f.z; x[q * 4 + 3] = f.w;
                }
                float m = x[0];
#pragma unroll
                for (int q = 1; q < 16; q++) m = fmaxf(m, x[q]);
                float se = 0.0f;
#pragma unroll
                for (int q = 0; q < 16; q++) se += __expf(x[q] - m);
                float logZ = m + __logf(se);
                float d = fminf(fmaxf(dist[ch_i], 0.0f), 16.0f - 1.0f - 0.01f);
                int tl = (int)d;
                int tr = min(tl + 1, 15);
                float wl = (float)tr - d;
                float wr = 1.0f - wl;
                dflv += (logZ - x[tl]) * wl + (logZ - x[tr]) * wr;
            }
            float img = fmaxf((float)img_p[0], 1.0f);
            float cx = (gt.x + gt.z) * 0.5f / img;
            float cy = (gt.y + gt.w) * 0.5f / img;
            float cn = fmaxf(sqrtf(cx * cx + cy * cy), 1e-12f);
            cx /= cn; cy /= cn;
            float p0 = prompt[(size_t)b * P + 0], p1 = prompt[(size_t)b * P + 1];
            float pn = fmaxf(sqrtf(p0 * p0 + p1 * p1), 1e-12f);
            float ctr = 1.0f - (cx * p0 + cy * p1) / pn;

            double* A = acc_s + b * 8;
            atomicAdd(&A[0], (double)(-s * ts));
            atomicAdd(&A[1], 1.0);
            atomicAdd(&A[2], (double)prob);
            atomicAdd(&A[4], (double)iou);
            atomicAdd(&A[5], (double)(1.0f - ciou));
            atomicAdd(&A[6], (double)dflv);
            atomicAdd(&A[7], (double)ctr);
        }
    }
    __syncthreads();
    for (int j = t; j < B * 8; j += FG_THREADS) {
        double val = acc_s[j];
        if (val != 0.0) atomicAdd(&g_acc[j], val);
    }
    __syncthreads();

    __shared__ int s_last;
    if (t == 0) {
        __threadfence();   // release our g_acc / g_key writes (one fence per block)
        s_last = (atomicAdd(&g_done, 1) == (int)gridDim.x - 1);
    }
    __syncthreads();
    if (!s_last) return;
    if (t == 0) __threadfence();   // acquire side
    __syncthreads();

    // ---- last block: finalize + reset ----
    __shared__ double pm[MAX_B], pi[MAX_B], pdf[MAX_B], pc[MAX_B];
    __shared__ double pt[MAX_B], pp[MAX_B], ptot[MAX_B], pmi[MAX_B];
    if (t < B) {
        const double* A = &g_acc[t * 8];
        double np = A[1];
        double den = fmax(np, 1.0);
        pm[t] = A[0] / (double)N;
        pt[t] = np;
        pp[t] = A[2];
        ptot[t] = A[3];
        pmi[t] = A[4];
        pi[t] = A[5] / den;
        pdf[t] = A[6] / (4.0 * den);
        pc[t] = A[7] / den;
    }
    __syncthreads();
    if (t == 0) {
        double match = 0, iou = 0, dfl = 0, ctr = 0, tp = 0, pos = 0, tot = 0, mi = 0;
        for (int b = 0; b < B; b++) {
            match += pm[b]; iou += pi[b]; dfl += pdf[b]; ctr += pc[b];
            tp += pt[b]; pos += pp[b]; tot += ptot[b]; mi += pmi[b];
        }
        double nb_ = (double)B;
        double tneg = (double)B * (double)N - tp;
        out[0] = (float)((1.0 * match + 7.5 * iou + 1.5 * dfl + 1.0 * ctr) / nb_);
        out[1] = (float)(match / nb_);
        out[2] = (float)(iou / nb_);
        out[3] = (float)(dfl / nb_);
        out[4] = (float)(ctr / nb_);
        out[5] = (float)tp;
        out[6] = (float)tneg;
        out[7] = (float)(pos / fmax(tp, 1.0));
        out[8] = (float)((tot - pos) / fmax(tneg, 1.0));
        out[9] = (float)(mi / fmax(tp, 1.0));
        g_cnt = 0;
        g_done = 0;
    }
    __syncthreads();
    for (int j = t; j < B * 8; j += FG_THREADS) g_acc[j] = 0.0;
}

extern "C" void kernel_launch(void* const* d_in, const int* in_sizes, int n_in,
                              void* d_out, int out_size) {
    const float* pred_boxes = (const float*)d_in[0];
    const float* pred_scores = (const float*)d_in[1];
    const float* anchors = (const float*)d_in[2];
    const float* strides = (const float*)d_in[3];
    const float* logits = (const float*)d_in[4];
    const float* prompt = (const float*)d_in[5];
    const float* gts = (const float*)d_in[6];
    const int* imgp = (const int*)d_in[7];

    int N = in_sizes[2] / 2;
    int B = in_sizes[1] / N;
    int G = in_sizes[6] / (4 * B);
    int P = in_sizes[5] / B;
    int BG = B * G;
    int total = B * N;
    int scoreBlocks = (total + 2047) / 2048;

    k_main<<<BG + scoreBlocks, 256>>>((const float4*)pred_boxes, pred_scores,
                                      (const float2*)anchors, (const float4*)gts,
                                      imgp, B, N, G, BG, total);
    int cap = BG * TOPK;
    if (cap > MAX_LIST) cap = MAX_LIST;
    k_fg<<<(cap + FG_THREADS - 1) / FG_THREADS, FG_THREADS>>>(
        (const float4*)pred_boxes, pred_scores,
        (const float2*)anchors, strides, logits, prompt,
        (const float4*)gts, imgp, (float*)d_out, B, N, G, P);
}

// round 9
// speedup vs baseline: 1.8155x; 1.0006x over previous
#include <cuda_runtime.h>
#include <math.h>

#define TOPK 13
#define EPSF 1e-7f
#define MAX_BN (1 << 20)
#define MAX_B 64
#define MAX_LIST 16384
#define FG_THREADS 64

typedef unsigned long long u64;

__device__ u64 g_key[MAX_BN];
__device__ double g_acc[MAX_B * 8];
__device__ int g_cnt;
__device__ int g_done;
__device__ int2 g_list[MAX_LIST];
__device__ float g_vals[MAX_LIST * 8];

__device__ __forceinline__ float iou_fn(float4 a, float4 b) {
    float x1 = fmaxf(a.x, b.x), y1 = fmaxf(a.y, b.y);
    float x2 = fminf(a.z, b.z), y2 = fminf(a.w, b.w);
    float inter = fmaxf(x2 - x1, 0.0f) * fmaxf(y2 - y1, 0.0f);
    float aa = (a.z - a.x) * (a.w - a.y);
    float ab = (b.z - b.x) * (b.w - b.y);
    return inter / (aa + ab - inter + EPSF);
}

// Fused: blocks [0, BG) assignment (one block per (image,gt));
// blocks [BG, ...) dense score reduction.
__global__ __launch_bounds__(256) void k_main(
    const float4* __restrict__ pred_boxes, const float* __restrict__ scores,
    const float2* __restrict__ anchors, const float* __restrict__ strides,
    const float* __restrict__ logits, const float* __restrict__ prompt,
    const float4* __restrict__ gts, const int* __restrict__ img_p,
    int B, int N, int G, int BG, int total, int P)
{
    int t = threadIdx.x;
    int lane = t & 31, wid = t >> 5;

    if ((int)blockIdx.x >= BG) {
        // ---------------- score role ----------------
        int sb = blockIdx.x - BG;
        int i0 = (sb * 256 + t) * 8;
        float bce = 0.0f, ps = 0.0f;
#pragma unroll
        for (int q = 0; q < 2; q++) {
            int base = i0 + q * 4;
            float sv[4];
            bool full = (base + 3 < total);
            if (full) {
                float4 s4 = *(const float4*)(scores + base);
                sv[0] = s4.x; sv[1] = s4.y; sv[2] = s4.z; sv[3] = s4.w;
            }
#pragma unroll
            for (int j = 0; j < 4; j++) {
                float s;
                bool valid = full;
                if (full) s = sv[j];
                else { int i = base + j; valid = (i < total); s = valid ? scores[i] : 0.0f; }
                if (valid) {
                    float e = __expf(-fabsf(s));
                    float pa = 1.0f / (1.0f + e);          // sigmoid(|s|)
                    bce += fmaxf(s, 0.0f) - __logf(pa);    // max(s,0)+log1p(e^-|s|)
                    ps += (s >= 0.0f) ? pa : 1.0f - pa;
                }
            }
        }
        __shared__ float r0[8], r1[8];
#pragma unroll
        for (int off = 16; off > 0; off >>= 1) {
            bce += __shfl_down_sync(0xFFFFFFFFu, bce, off);
            ps  += __shfl_down_sync(0xFFFFFFFFu, ps, off);
        }
        if (lane == 0) { r0[wid] = bce; r1[wid] = ps; }
        __syncthreads();
        if (t == 0) {
            float a = 0.0f, p = 0.0f;
            for (int w = 0; w < 8; w++) { a += r0[w]; p += r1[w]; }
            atomicAdd(&g_acc[0], (double)a);   // global bce0
            atomicAdd(&g_acc[3], (double)p);   // global prob sum
        }
        return;
    }

    // ---------------- assign role ----------------
    int bg = blockIdx.x;
    int b = bg / G, g = bg % G;
    float4 gt = gts[bg];

    u64 v[TOPK];
#pragma unroll
    for (int j = 0; j < TOPK; j++) v[j] = 0ULL;

    const float4* pb_b = pred_boxes + (size_t)b * N;
    const float*  sc_b = scores + (size_t)b * N;

    int img = img_p[0];
    int n0 = img / 8, n1 = img / 16, n2 = img / 32;
    bool structured = (n0 * n0 + n1 * n1 + n2 * n2 == N) && img > 0;

    if (structured) {
        int nn[3] = {n0, n1, n2};
        int base[3] = {0, n0 * n0, n0 * n0 + n1 * n1};
        int c0[3], r0a[3], cw[3], m[3];
        int M = 0;
#pragma unroll
        for (int sc = 0; sc < 3; sc++) {
            float s = (float)(8 << sc);
            int n = nn[sc];
            int cl = max((int)floorf(gt.x / s - 0.5f) - 1, 0);
            int ch = min((int)ceilf(gt.z / s - 0.5f) + 1, n - 1);
            int rl = max((int)floorf(gt.y / s - 0.5f) - 1, 0);
            int rh = min((int)ceilf(gt.w / s - 0.5f) + 1, n - 1);
            int ccw = ch - cl + 1, crh = rh - rl + 1;
            if (ccw < 0) ccw = 0;
            if (crh < 0) crh = 0;
            c0[sc] = cl; r0a[sc] = rl; cw[sc] = ccw;
            m[sc] = ccw * crh;
            M += m[sc];
        }
        for (int k = t; k < M; k += 256) {
            int sc = 0, rel = k;
            while (rel >= m[sc]) { rel -= m[sc]; sc++; }
            int row = rel / cw[sc] + r0a[sc];
            int col = rel % cw[sc] + c0[sc];
            int a = base[sc] + row * nn[sc] + col;
            float2 an = anchors[a];
            if (an.x >= gt.x && an.x <= gt.z && an.y >= gt.y && an.y <= gt.w) {
                float4 pb = pb_b[a];
                float iou = iou_fn(pb, gt);
                float s = sc_b[a];
                float prob = 1.0f / (1.0f + __expf(-s));
                float i2 = iou * iou;
                float align = prob * (i2 * i2 * i2);
                u64 key = ((u64)__float_as_uint(align) << 32)
                        | (u64)(0xFFFFFFFFu - (unsigned)a);
                if (key > v[TOPK - 1]) {
#pragma unroll
                    for (int j = 0; j < TOPK; j++)
                        if (key > v[j]) { u64 tv = v[j]; v[j] = key; key = tv; }
                }
            }
        }
    } else {
        for (int a = t; a < N; a += 256) {
            float2 an = anchors[a];
            if (an.x >= gt.x && an.x <= gt.z && an.y >= gt.y && an.y <= gt.w) {
                float4 pb = pb_b[a];
                float iou = iou_fn(pb, gt);
                float s = sc_b[a];
                float prob = 1.0f / (1.0f + __expf(-s));
                float i2 = iou * iou;
                float align = prob * (i2 * i2 * i2);
                u64 key = ((u64)__float_as_uint(align) << 32)
                        | (u64)(0xFFFFFFFFu - (unsigned)a);
                if (key > v[TOPK - 1]) {
#pragma unroll
                    for (int j = 0; j < TOPK; j++)
                        if (key > v[j]) { u64 tv = v[j]; v[j] = key; key = tv; }
                }
            }
        }
    }

    // ---- level 1: per-warp top-13 (no block syncs) ----
    __shared__ u64 s_all[8 * TOPK];
    {
        u64 myw = 0ULL;
        int ptr = 0;
        for (int r = 0; r < TOPK; r++) {
            u64 h = (ptr < TOPK) ? v[ptr] : 0ULL;
            int src = lane;
#pragma unroll
            for (int off = 16; off > 0; off >>= 1) {
                u64 o = __shfl_down_sync(0xFFFFFFFFu, h, off);
                int os = __shfl_down_sync(0xFFFFFFFFu, src, off);
                if (o > h) { h = o; src = os; }
            }
            u64 hb = __shfl_sync(0xFFFFFFFFu, h, 0);
            int sl = __shfl_sync(0xFFFFFFFFu, src, 0);
            if (hb == 0ULL) break;
            if (lane == sl) ptr++;
            if (lane == r) myw = hb;
        }
        if (lane < TOPK) s_all[wid * TOPK + lane] = myw;   // sorted desc per warp
    }
    __syncthreads();
    if (wid != 0) return;

    // ---- level 2: warp 0 merges 8 sorted lists of 13 ----
    u64 myw = 0ULL;
    {
        int ptr = 0;   // per-lane head pointer (lanes 0..7 own a list)
        for (int r = 0; r < TOPK; r++) {
            u64 h = (lane < 8 && ptr < TOPK) ? s_all[lane * TOPK + ptr] : 0ULL;
            int src = lane;
#pragma unroll
            for (int off = 4; off > 0; off >>= 1) {
                u64 o = __shfl_down_sync(0xFFFFFFFFu, h, off);
                int os = __shfl_down_sync(0xFFFFFFFFu, src, off);
                if (o > h) { h = o; src = os; }
            }
            u64 hb = __shfl_sync(0xFFFFFFFFu, h, 0);
            int sl = __shfl_sync(0xFFFFFFFFu, src, 0);
            if (hb == 0ULL) break;
            if (lane == sl) ptr++;
            if (lane == r) myw = hb;
        }
    }

    // ---- winner lanes: scatter key + speculative loss precompute ----
    if (lane < TOPK && myw != 0ULL) {
        unsigned bits = (unsigned)(myw >> 32);
        int a = (int)(0xFFFFFFFFu - (unsigned)(myw & 0xFFFFFFFFull));
        int idx = b * N + a;
        u64 key = ((u64)(bits + 1u) << 32) | (u64)(0xFFFFFFFFu - (unsigned)g);
        atomicMax(&g_key[idx], key);
        int pos = atomicAdd(&g_cnt, 1);
        if (pos < MAX_LIST) {
            g_list[pos] = make_int2(idx, g);
            // full loss terms for (idx, g); used iff this entry wins the argmax
            float4 pb = pb_b[a];
            float s = sc_b[a];
            float prob = 1.0f / (1.0f + __expf(-s));
            float iou = iou_fn(pb, gt);
            float ts = fmaxf(iou, 0.1f);
            float cw = fmaxf(pb.z, gt.z) - fminf(pb.x, gt.x);
            float ch = fmaxf(pb.w, gt.w) - fminf(pb.y, gt.y);
            float c2 = cw * cw + ch * ch + EPSF;
            float dx = gt.x + gt.z - pb.x - pb.z;
            float dy = gt.y + gt.w - pb.y - pb.w;
            float rho2 = (dx * dx + dy * dy) * 0.25f;
            float w1 = pb.z - pb.x, h1 = pb.w - pb.y + EPSF;
            float w2 = gt.z - gt.x, h2 = gt.w - gt.y + EPSF;
            float dat = atanf(w2 / h2) - atanf(w1 / h1);
            float vv = 0.40528473456935109f * dat * dat;
            float alpha = vv / (vv - iou + 1.0f + EPSF);
            float ciou = iou - rho2 / c2 - vv * alpha;
            float2 an = anchors[a];
            float st = strides[a];
            float dist[4];
            dist[0] = (an.x - gt.x) / st;
            dist[1] = (an.y - gt.y) / st;
            dist[2] = (gt.z - an.x) / st;
            dist[3] = (gt.w - an.y) / st;
            const float* lg = logits + (size_t)idx * 64;
            float dflv = 0.0f;
#pragma unroll
            for (int ch_i = 0; ch_i < 4; ch_i++) {
                float x[16];
                const float4* l4 = (const float4*)(lg + ch_i * 16);
#pragma unroll
                for (int q = 0; q < 4; q++) {
                    float4 f = l4[q];
                    x[q * 4 + 0] = f.x; x[q * 4 + 1] = f.y;
                    x[q * 4 + 2] = f.z; x[q * 4 + 3] = f.w;
                }
                float m = x[0];
#pragma unroll
                for (int q = 1; q < 16; q++) m = fmaxf(m, x[q]);
                float se = 0.0f;
#pragma unroll
                for (int q = 0; q < 16; q++) se += __expf(x[q] - m);
                float logZ = m + __logf(se);
                float d = fminf(fmaxf(dist[ch_i], 0.0f), 16.0f - 1.0f - 0.01f);
                int tl = (int)d;
                int tr = min(tl + 1, 15);
                float wl = (float)tr - d;
                float wr = 1.0f - wl;
                dflv += (logZ - x[tl]) * wl + (logZ - x[tr]) * wr;
            }
            float imgf = fmaxf((float)img, 1.0f);
            float cx = (gt.x + gt.z) * 0.5f / imgf;
            float cy = (gt.y + gt.w) * 0.5f / imgf;
            float cn = fmaxf(sqrtf(cx * cx + cy * cy), 1e-12f);
            cx /= cn; cy /= cn;
            float p0 = prompt[(size_t)b * P + 0], p1 = prompt[(size_t)b * P + 1];
            float pn = fmaxf(sqrtf(p0 * p0 + p1 * p1), 1e-12f);
            float ctr = 1.0f - (cx * p0 + cy * p1) / pn;

            float* V = g_vals + (size_t)pos * 8;
            V[0] = -s * ts;          // BCE correction
            V[1] = 1.0f;             // n_pos
            V[2] = prob;             // pos prob
            V[3] = 0.0f;
            V[4] = iou;              // matched iou
            V[5] = 1.0f - ciou;      // iou loss
            V[6] = dflv;             // dfl
            V[7] = ctr;              // contrast
        }
    }
}

// Winner check + accumulate precomputed values; last block finalizes.
__global__ __launch_bounds__(FG_THREADS) void k_fg(
    float* __restrict__ out, int B, int N)
{
    __shared__ double acc_s[MAX_B * 8];
    int t = threadIdx.x;
    for (int i = t; i < B * 8; i += FG_THREADS) acc_s[i] = 0.0;
    __syncthreads();

    int i = blockIdx.x * FG_THREADS + t;
    int cnt = g_cnt;
    if (cnt > MAX_LIST) cnt = MAX_LIST;
    if (i < cnt) {
        int2 e = g_list[i];
        int idx = e.x, g = e.y;
        u64 key = g_key[idx];
        int gw = (int)(0xFFFFFFFFu - (unsigned)(key & 0xFFFFFFFFull));
        if (key != 0ULL && gw == g) {
            g_key[idx] = 0ULL;    // exactly-once cleanup by the winner
            const float* V = g_vals + (size_t)i * 8;
            float4 v0 = *(const float4*)V;
            float4 v1 = *(const float4*)(V + 4);
            int b = idx / N;
            double* A = acc_s + b * 8;
            atomicAdd(&A[0], (double)v0.x);
            atomicAdd(&A[1], 1.0);
            atomicAdd(&A[2], (double)v0.z);
            atomicAdd(&A[4], (double)v1.x);
            atomicAdd(&A[5], (double)v1.y);
            atomicAdd(&A[6], (double)v1.z);
            atomicAdd(&A[7], (double)v1.w);
        }
    }
    __syncthreads();
    for (int j = t; j < B * 8; j += FG_THREADS) {
        double val = acc_s[j];
        if (val != 0.0) atomicAdd(&g_acc[j], val);
    }
    __syncthreads();

    __shared__ int s_last;
    if (t == 0) {
        __threadfence();   // release g_acc / g_key writes (one fence per block)
        s_last = (atomicAdd(&g_done, 1) == (int)gridDim.x - 1);
    }
    __syncthreads();
    if (!s_last) return;
    if (t == 0) __threadfence();   // acquire side
    __syncthreads();

    // ---- last block: finalize + reset ----
    __shared__ double pm[MAX_B], pi[MAX_B], pdf[MAX_B], pc[MAX_B];
    __shared__ double pt[MAX_B], pp[MAX_B], ptot[MAX_B], pmi[MAX_B];
    if (t < B) {
        const double* A = &g_acc[t * 8];
        double np = A[1];
        double den = fmax(np, 1.0);
        pm[t] = A[0] / (double)N;
        pt[t] = np;
        pp[t] = A[2];
        ptot[t] = A[3];
        pmi[t] = A[4];
        pi[t] = A[5] / den;
        pdf[t] = A[6] / (4.0 * den);
        pc[t] = A[7] / den;
    }
    __syncthreads();
    if (t == 0) {
        double match = 0, iou = 0, dfl = 0, ctr = 0, tp = 0, pos = 0, tot = 0, mi = 0;
        for (int b = 0; b < B; b++) {
            match += pm[b]; iou += pi[b]; dfl += pdf[b]; ctr += pc[b];
            tp += pt[b]; pos += pp[b]; tot += ptot[b]; mi += pmi[b];
        }
        double nb_ = (double)B;
        double tneg = (double)B * (double)N - tp;
        out[0] = (float)((1.0 * match + 7.5 * iou + 1.5 * dfl + 1.0 * ctr) / nb_);
        out[1] = (float)(match / nb_);
        out[2] = (float)(iou / nb_);
        out[3] = (float)(dfl / nb_);
        out[4] = (float)(ctr / nb_);
        out[5] = (float)tp;
        out[6] = (float)tneg;
        out[7] = (float)(pos / fmax(tp, 1.0));
        out[8] = (float)((tot - pos) / fmax(tneg, 1.0));
        out[9] = (float)(mi / fmax(tp, 1.0));
        g_cnt = 0;
        g_done = 0;
    }
    __syncthreads();
    for (int j = t; j < B * 8; j += FG_THREADS) g_acc[j] = 0.0;
}

extern "C" void kernel_launch(void* const* d_in, const int* in_sizes, int n_in,
                              void* d_out, int out_size) {
    const float* pred_boxes = (const float*)d_in[0];
    const float* pred_scores = (const float*)d_in[1];
    const float* anchors = (const float*)d_in[2];
    const float* strides = (const float*)d_in[3];
    const float* logits = (const float*)d_in[4];
    const float* prompt = (const float*)d_in[5];
    const float* gts = (const float*)d_in[6];
    const int* imgp = (const int*)d_in[7];

    int N = in_sizes[2] / 2;
    int B = in_sizes[1] / N;
    int G = in_sizes[6] / (4 * B);
    int P = in_sizes[5] / B;
    int BG = B * G;
    int total = B * N;
    int scoreBlocks = (total + 2047) / 2048;

    k_main<<<BG + scoreBlocks, 256>>>((const float4*)pred_boxes, pred_scores,
                                      (const float2*)anchors, strides, logits, prompt,
                                      (const float4*)gts, imgp,
                                      B, N, G, BG, total, P);
    int cap = BG * TOPK;
    if (cap > MAX_LIST) cap = MAX_LIST;
    k_fg<<<(cap + FG_THREADS - 1) / FG_THREADS, FG_THREADS>>>(
        (float*)d_out, B, N);
}